// round 1
// baseline (speedup 1.0000x reference)
#include <cuda_runtime.h>
#include <cuda_bf16.h>

#define BB 4
#define TT 4096
#define DD 256
#define KS 64           // K_SIZE == V_SIZE == 64
#define OUTW 320        // DD + KS

// scratch for projected q/k/v: [3][B*T*64] fp32  (order: 0=k, 1=q, 2=v)
__device__ float g_qkv[3][(size_t)BB * TT * KS];

// ---------------------------------------------------------------------------
// Projection kernel: out_mat = X @ W  for W in {key_w, query_w, value_w}
// grid: (B*T/64, 3), block: 256 threads. Also copies X into out[:, :256] (y==0).
// smem: Xs transposed [256][68] (69632B) + Ws [256][64] (65536B) = 135168B
// ---------------------------------------------------------------------------
__global__ __launch_bounds__(256)
void proj_kernel(const float* __restrict__ x,
                 const float* __restrict__ kw,
                 const float* __restrict__ qw,
                 const float* __restrict__ vw,
                 float* __restrict__ out)
{
    extern __shared__ float sm[];
    float* Xs = sm;                 // [256][68], d-major: Xs[d*68 + r]
    float* Ws = sm + 256 * 68;      // [256][64] natural: Ws[d*64 + c]

    const int tid = threadIdx.x;
    const int y   = blockIdx.y;
    const int R0  = blockIdx.x * 64;

    const float* w  = (y == 0) ? kw : ((y == 1) ? qw : vw);
    float* dst      = g_qkv[y];

    // Load X tile (64 rows x 256 dims), transposed into Xs.
    // Thread owns one d-column (d = tid), walks 64 rows: global reads coalesced.
    {
        const int d0 = tid;         // 0..255
        #pragma unroll 4
        for (int r = 0; r < 64; ++r) {
            float v = x[(size_t)(R0 + r) * DD + d0];
            Xs[d0 * 68 + r] = v;
            if (y == 0) out[(size_t)(R0 + r) * OUTW + d0] = v;  // fused concat copy
        }
    }
    // Load W (256x64), natural layout, fully coalesced.
    #pragma unroll 4
    for (int i = tid; i < 256 * 64; i += 256) {
        Ws[i] = w[i];
    }
    __syncthreads();

    const int ty = tid >> 4, tx = tid & 15;
    const int r4 = ty * 4, c4 = tx * 4;

    float acc[4][4] = {};
    #pragma unroll 4
    for (int d = 0; d < 256; ++d) {
        float4 a  = *(const float4*)&Xs[d * 68 + r4];
        float4 wv = *(const float4*)&Ws[d * 64 + c4];
        acc[0][0] += a.x * wv.x; acc[0][1] += a.x * wv.y; acc[0][2] += a.x * wv.z; acc[0][3] += a.x * wv.w;
        acc[1][0] += a.y * wv.x; acc[1][1] += a.y * wv.y; acc[1][2] += a.y * wv.z; acc[1][3] += a.y * wv.w;
        acc[2][0] += a.z * wv.x; acc[2][1] += a.z * wv.y; acc[2][2] += a.z * wv.z; acc[2][3] += a.z * wv.w;
        acc[3][0] += a.w * wv.x; acc[3][1] += a.w * wv.y; acc[3][2] += a.w * wv.z; acc[3][3] += a.w * wv.w;
    }

    #pragma unroll
    for (int i = 0; i < 4; ++i) {
        float4 r = make_float4(acc[i][0], acc[i][1], acc[i][2], acc[i][3]);
        *(float4*)&dst[(size_t)(R0 + r4 + i) * KS + c4] = r;
    }
}

// ---------------------------------------------------------------------------
// Flash-attention kernel (fp32, causal). grid: (T/64, B), block: 256 threads.
// Tiles: 64 q-rows x 64 k-cols, 4x4 microtile per thread.
// smem: Qt[64][68] + Kt[64][68] + Ps[64][68] + Vs[64][64] = 68608B
// ---------------------------------------------------------------------------
__global__ __launch_bounds__(256)
void attn_kernel(float* __restrict__ out)
{
    extern __shared__ float sm[];
    float* Qt = sm;                  // d-major: Qt[d*68 + r]
    float* Kt = Qt + 64 * 68;        // d-major: Kt[d*68 + c]
    float* Ps = Kt + 64 * 68;        // row-major: Ps[r*68 + s]
    float* Vs = Ps + 64 * 68;        // natural:  Vs[s*64 + v]

    const int tid = threadIdx.x;
    const int qt  = blockIdx.x;
    const int b   = blockIdx.y;
    const int qb  = qt * 64;

    const float* gq = g_qkv[1] + (size_t)b * TT * KS;
    const float* gk = g_qkv[0] + (size_t)b * TT * KS;
    const float* gv = g_qkv[2] + (size_t)b * TT * KS;

    // Load Q tile transposed (one-time).
    #pragma unroll 4
    for (int i = tid; i < 64 * 64; i += 256) {
        int r = i >> 6, d = i & 63;
        Qt[d * 68 + r] = gq[(size_t)(qb + r) * KS + d];
    }

    const int ty = tid >> 4, tx = tid & 15;
    const int r4 = ty * 4,  c4 = tx * 4;

    float o[4][4] = {};
    float m[4] = { -1e30f, -1e30f, -1e30f, -1e30f };
    float l[4] = {};

    const float LOG2E = 1.44269504088896f;

    for (int kt = 0; kt <= qt; ++kt) {
        const int kb = kt * 64;
        __syncthreads();   // prev iter's Ps/Vs reads done before overwrite
        #pragma unroll 4
        for (int i = tid; i < 64 * 64; i += 256) {
            int r = i >> 6, d = i & 63;
            Kt[d * 68 + r] = gk[(size_t)(kb + r) * KS + d];
            Vs[i]          = gv[(size_t)kb * KS + i];
        }
        __syncthreads();

        // S = Q K^T  (4x4 microtile, dot over d=0..63)
        float s[4][4] = {};
        #pragma unroll 8
        for (int d = 0; d < 64; ++d) {
            float4 a = *(const float4*)&Qt[d * 68 + r4];
            float4 k = *(const float4*)&Kt[d * 68 + c4];
            s[0][0] += a.x * k.x; s[0][1] += a.x * k.y; s[0][2] += a.x * k.z; s[0][3] += a.x * k.w;
            s[1][0] += a.y * k.x; s[1][1] += a.y * k.y; s[1][2] += a.y * k.z; s[1][3] += a.y * k.w;
            s[2][0] += a.z * k.x; s[2][1] += a.z * k.y; s[2][2] += a.z * k.z; s[2][3] += a.z * k.w;
            s[3][0] += a.w * k.x; s[3][1] += a.w * k.y; s[3][2] += a.w * k.z; s[3][3] += a.w * k.w;
        }

        const bool diag = (kt == qt);
        float mn[4];
        #pragma unroll
        for (int i = 0; i < 4; ++i) {
            float mx = -1e30f;
            #pragma unroll
            for (int j = 0; j < 4; ++j) {
                float v = s[i][j] * 0.125f;                 // 1/sqrt(64)
                if (diag && (c4 + j > r4 + i)) v = -1e30f;  // causal mask
                s[i][j] = v;
                mx = fmaxf(mx, v);
            }
            // reduce max across the 16-lane row group
            #pragma unroll
            for (int off = 8; off > 0; off >>= 1)
                mx = fmaxf(mx, __shfl_xor_sync(0xffffffffu, mx, off));
            mn[i] = fmaxf(m[i], mx);
        }

        #pragma unroll
        for (int i = 0; i < 4; ++i) {
            float alpha = exp2f((m[i] - mn[i]) * LOG2E);
            m[i] = mn[i];
            l[i] *= alpha;
            float rs = 0.f;
            #pragma unroll
            for (int j = 0; j < 4; ++j) {
                float p = exp2f((s[i][j] - mn[i]) * LOG2E);
                s[i][j] = p;
                rs += p;
                o[i][j] *= alpha;
            }
            #pragma unroll
            for (int off = 8; off > 0; off >>= 1)
                rs += __shfl_xor_sync(0xffffffffu, rs, off);
            l[i] += rs;
            *(float4*)&Ps[(r4 + i) * 68 + c4] =
                make_float4(s[i][0], s[i][1], s[i][2], s[i][3]);
        }
        __syncthreads();

        // O += P V  (dot over s=0..63)
        #pragma unroll 4
        for (int si = 0; si < 64; ++si) {
            float4 v = *(const float4*)&Vs[si * 64 + c4];
            float p0 = Ps[(r4 + 0) * 68 + si];
            float p1 = Ps[(r4 + 1) * 68 + si];
            float p2 = Ps[(r4 + 2) * 68 + si];
            float p3 = Ps[(r4 + 3) * 68 + si];
            o[0][0] += p0 * v.x; o[0][1] += p0 * v.y; o[0][2] += p0 * v.z; o[0][3] += p0 * v.w;
            o[1][0] += p1 * v.x; o[1][1] += p1 * v.y; o[1][2] += p1 * v.z; o[1][3] += p1 * v.w;
            o[2][0] += p2 * v.x; o[2][1] += p2 * v.y; o[2][2] += p2 * v.z; o[2][3] += p2 * v.w;
            o[3][0] += p3 * v.x; o[3][1] += p3 * v.y; o[3][2] += p3 * v.z; o[3][3] += p3 * v.w;
        }
    }

    // epilogue: normalize and write read-values into out[:, 256:320]
    const size_t base = (size_t)b * TT + qb;
    #pragma unroll
    for (int i = 0; i < 4; ++i) {
        float inv = 1.0f / l[i];
        float4 r = make_float4(o[i][0] * inv, o[i][1] * inv,
                               o[i][2] * inv, o[i][3] * inv);
        *(float4*)&out[(base + r4 + i) * OUTW + DD + c4] = r;
    }
}

// ---------------------------------------------------------------------------
extern "C" void kernel_launch(void* const* d_in, const int* in_sizes, int n_in,
                              void* d_out, int out_size)
{
    const float* x  = (const float*)d_in[0];
    const float* kw = (const float*)d_in[1];
    const float* qw = (const float*)d_in[2];
    const float* vw = (const float*)d_in[3];
    float* out = (float*)d_out;

    const int PROJ_SMEM = (256 * 68 + 256 * 64) * 4;          // 135168
    const int ATTN_SMEM = (64 * 68 * 3 + 64 * 64) * 4;        // 68608

    cudaFuncSetAttribute(proj_kernel, cudaFuncAttributeMaxDynamicSharedMemorySize, PROJ_SMEM);
    cudaFuncSetAttribute(attn_kernel, cudaFuncAttributeMaxDynamicSharedMemorySize, ATTN_SMEM);

    proj_kernel<<<dim3((BB * TT) / 64, 3), 256, PROJ_SMEM>>>(x, kw, qw, vw, out);
    attn_kernel<<<dim3(TT / 64, BB), 256, ATTN_SMEM>>>(out);
}